// round 1
// baseline (speedup 1.0000x reference)
#include <cuda_runtime.h>
#include <math.h>

// Problem constants
#define BB 4
#define TT 2048
#define DD 1024
#define MTOT (BB * TT)          // 8192 rows of x
#define SCALE (0.03125f)        // 1/sqrt(1024)

// Scratch (device globals; no allocation allowed)
__device__ float g_q[MTOT * DD];
__device__ float g_k[MTOT * DD];
__device__ float g_v[MTOT * DD];
__device__ float g_s[BB * TT * TT];   // scores -> attention probs (in-place)

// ---------------------------------------------------------------------------
// Tiled SGEMM parameters: 128x128 C-tile, K-step 8, 8x8 per thread, 256 thr.
// ---------------------------------------------------------------------------
#define BM 128
#define BN 128
#define BK 8
#define TM 8
#define TN 8

// ---------------------------------------------------------------------------
// Kernel 1: QKV projection.  C = X[8192,1024] * W[1024,1024]
// blockIdx.z selects (Wq->g_q, Wk->g_k, Wv->g_v).
// ---------------------------------------------------------------------------
__global__ void __launch_bounds__(256)
proj_kernel(const float* __restrict__ x,
            const float* __restrict__ Wq,
            const float* __restrict__ Wk,
            const float* __restrict__ Wv)
{
    const int K = DD, N = DD;
    const float* Bmat;
    float* C;
    if (blockIdx.z == 0)      { Bmat = Wq; C = g_q; }
    else if (blockIdx.z == 1) { Bmat = Wk; C = g_k; }
    else                      { Bmat = Wv; C = g_v; }

    const int rowBase = blockIdx.y * BM;
    const int colBase = blockIdx.x * BN;
    const int tid = threadIdx.x;
    const int tx = tid % 16, ty = tid / 16;

    __shared__ float As[BK][BM];
    __shared__ float Bs[BK][BN];

    // A-tile load mapping: 128 rows x 8 cols = 256 float4
    const int aRow = tid >> 1;
    const int aCol = (tid & 1) * 4;
    // B-tile load mapping: 8 rows x 128 cols = 256 float4
    const int bRow = tid >> 5;
    const int bCol = (tid & 31) * 4;

    float acc[TM][TN];
#pragma unroll
    for (int i = 0; i < TM; i++)
#pragma unroll
        for (int j = 0; j < TN; j++) acc[i][j] = 0.f;

    for (int k0 = 0; k0 < K; k0 += BK) {
        float4 av = *reinterpret_cast<const float4*>(
            &x[(rowBase + aRow) * K + k0 + aCol]);
        As[aCol + 0][aRow] = av.x;
        As[aCol + 1][aRow] = av.y;
        As[aCol + 2][aRow] = av.z;
        As[aCol + 3][aRow] = av.w;
        *reinterpret_cast<float4*>(&Bs[bRow][bCol]) =
            *reinterpret_cast<const float4*>(&Bmat[(k0 + bRow) * N + colBase + bCol]);
        __syncthreads();
#pragma unroll
        for (int kk = 0; kk < BK; kk++) {
            float a[TM], b[TN];
#pragma unroll
            for (int i = 0; i < TM; i++) a[i] = As[kk][ty * TM + i];
#pragma unroll
            for (int j = 0; j < TN; j++) b[j] = Bs[kk][tx * TN + j];
#pragma unroll
            for (int i = 0; i < TM; i++)
#pragma unroll
                for (int j = 0; j < TN; j++) acc[i][j] += a[i] * b[j];
        }
        __syncthreads();
    }

#pragma unroll
    for (int i = 0; i < TM; i++) {
        const int r = rowBase + ty * TM + i;
#pragma unroll
        for (int j = 0; j < TN; j += 4) {
            float4 v;
            v.x = acc[i][j + 0]; v.y = acc[i][j + 1];
            v.z = acc[i][j + 2]; v.w = acc[i][j + 3];
            *reinterpret_cast<float4*>(&C[r * N + colBase + tx * TN + j]) = v;
        }
    }
}

// ---------------------------------------------------------------------------
// Kernel 2: scores = (Q Kt) * SCALE, per batch; NT gemm.
// Skip blocks entirely above the diagonal. Diagonal-tile garbage above the
// diagonal is never read (softmax only reads k <= q).
// ---------------------------------------------------------------------------
__global__ void __launch_bounds__(256)
scores_kernel()
{
    const int b = blockIdx.z;
    const int qBase = blockIdx.y * BM;
    const int kBase = blockIdx.x * BN;
    if (kBase > qBase + BM - 1) return;  // fully masked block

    const float* Qm = g_q + b * TT * DD;
    const float* Km = g_k + b * TT * DD;
    float* S = g_s + b * TT * TT;

    const int tid = threadIdx.x;
    const int tx = tid % 16, ty = tid / 16;

    __shared__ float As[BK][BM];
    __shared__ float Bs[BK][BN];

    const int aRow = tid >> 1;
    const int aCol = (tid & 1) * 4;

    float acc[TM][TN];
#pragma unroll
    for (int i = 0; i < TM; i++)
#pragma unroll
        for (int j = 0; j < TN; j++) acc[i][j] = 0.f;

    for (int k0 = 0; k0 < DD; k0 += BK) {
        float4 av = *reinterpret_cast<const float4*>(
            &Qm[(qBase + aRow) * DD + k0 + aCol]);
        As[aCol + 0][aRow] = av.x;
        As[aCol + 1][aRow] = av.y;
        As[aCol + 2][aRow] = av.z;
        As[aCol + 3][aRow] = av.w;
        float4 bv = *reinterpret_cast<const float4*>(
            &Km[(kBase + aRow) * DD + k0 + aCol]);
        Bs[aCol + 0][aRow] = bv.x;
        Bs[aCol + 1][aRow] = bv.y;
        Bs[aCol + 2][aRow] = bv.z;
        Bs[aCol + 3][aRow] = bv.w;
        __syncthreads();
#pragma unroll
        for (int kk = 0; kk < BK; kk++) {
            float a[TM], b2[TN];
#pragma unroll
            for (int i = 0; i < TM; i++) a[i] = As[kk][ty * TM + i];
#pragma unroll
            for (int j = 0; j < TN; j++) b2[j] = Bs[kk][tx * TN + j];
#pragma unroll
            for (int i = 0; i < TM; i++)
#pragma unroll
                for (int j = 0; j < TN; j++) acc[i][j] += a[i] * b2[j];
        }
        __syncthreads();
    }

#pragma unroll
    for (int i = 0; i < TM; i++) {
        const int r = qBase + ty * TM + i;
#pragma unroll
        for (int j = 0; j < TN; j += 4) {
            float4 v;
            v.x = acc[i][j + 0] * SCALE; v.y = acc[i][j + 1] * SCALE;
            v.z = acc[i][j + 2] * SCALE; v.w = acc[i][j + 3] * SCALE;
            *reinterpret_cast<float4*>(&S[r * TT + kBase + tx * TN + j]) = v;
        }
    }
}

// ---------------------------------------------------------------------------
// Kernel 3: causal softmax, in-place on g_s. One block per (b, q) row.
// Writes zeros for k > q so the PV gemm can read full tiles.
// ---------------------------------------------------------------------------
__global__ void __launch_bounds__(256)
softmax_kernel()
{
    const int row = blockIdx.x;       // b*TT + q
    const int q = row % TT;
    float* s = g_s + (long)row * TT;
    const int n = q + 1;
    const int tid = threadIdx.x;

    __shared__ float red[256];

    // max over valid region
    float m = -INFINITY;
    for (int i = tid; i < n; i += 256) m = fmaxf(m, s[i]);
    red[tid] = m;
    __syncthreads();
    for (int off = 128; off > 0; off >>= 1) {
        if (tid < off) red[tid] = fmaxf(red[tid], red[tid + off]);
        __syncthreads();
    }
    m = red[0];
    __syncthreads();

    // sum of exp
    float sum = 0.f;
    for (int i = tid; i < n; i += 256) sum += __expf(s[i] - m);
    red[tid] = sum;
    __syncthreads();
    for (int off = 128; off > 0; off >>= 1) {
        if (tid < off) red[tid] += red[tid + off];
        __syncthreads();
    }
    const float inv = 1.f / red[0];

    for (int i = tid; i < TT; i += 256)
        s[i] = (i < n) ? __expf(s[i] - m) * inv : 0.f;
}

// ---------------------------------------------------------------------------
// Kernel 4: out = att @ V per batch (NN gemm), K-loop bounded by causality.
// ---------------------------------------------------------------------------
__global__ void __launch_bounds__(256)
pv_kernel(float* __restrict__ out)
{
    const int b = blockIdx.z;
    const int rowBase = blockIdx.y * BM;     // q
    const int colBase = blockIdx.x * BN;     // e
    const int kmax = (blockIdx.y + 1) * BM;  // att[q,k]=0 for k>q

    const float* A = g_s + b * TT * TT;
    const float* Bmat = g_v + b * TT * DD;
    float* C = out + b * TT * DD;

    const int tid = threadIdx.x;
    const int tx = tid % 16, ty = tid / 16;

    __shared__ float As[BK][BM];
    __shared__ float Bs[BK][BN];

    const int aRow = tid >> 1;
    const int aCol = (tid & 1) * 4;
    const int bRow = tid >> 5;
    const int bCol = (tid & 31) * 4;

    float acc[TM][TN];
#pragma unroll
    for (int i = 0; i < TM; i++)
#pragma unroll
        for (int j = 0; j < TN; j++) acc[i][j] = 0.f;

    for (int k0 = 0; k0 < kmax; k0 += BK) {
        float4 av = *reinterpret_cast<const float4*>(
            &A[(rowBase + aRow) * TT + k0 + aCol]);
        As[aCol + 0][aRow] = av.x;
        As[aCol + 1][aRow] = av.y;
        As[aCol + 2][aRow] = av.z;
        As[aCol + 3][aRow] = av.w;
        *reinterpret_cast<float4*>(&Bs[bRow][bCol]) =
            *reinterpret_cast<const float4*>(&Bmat[(k0 + bRow) * DD + colBase + bCol]);
        __syncthreads();
#pragma unroll
        for (int kk = 0; kk < BK; kk++) {
            float a[TM], b2[TN];
#pragma unroll
            for (int i = 0; i < TM; i++) a[i] = As[kk][ty * TM + i];
#pragma unroll
            for (int j = 0; j < TN; j++) b2[j] = Bs[kk][tx * TN + j];
#pragma unroll
            for (int i = 0; i < TM; i++)
#pragma unroll
                for (int j = 0; j < TN; j++) acc[i][j] += a[i] * b2[j];
        }
        __syncthreads();
    }

#pragma unroll
    for (int i = 0; i < TM; i++) {
        const int r = rowBase + ty * TM + i;
#pragma unroll
        for (int j = 0; j < TN; j += 4) {
            float4 v;
            v.x = acc[i][j + 0]; v.y = acc[i][j + 1];
            v.z = acc[i][j + 2]; v.w = acc[i][j + 3];
            *reinterpret_cast<float4*>(&C[r * DD + colBase + tx * TN + j]) = v;
        }
    }
}

// ---------------------------------------------------------------------------
extern "C" void kernel_launch(void* const* d_in, const int* in_sizes, int n_in,
                              void* d_out, int out_size)
{
    const float* x  = (const float*)d_in[0];
    const float* Wq = (const float*)d_in[1];
    const float* Wk = (const float*)d_in[2];
    const float* Wv = (const float*)d_in[3];
    float* out = (float*)d_out;

    // 1) QKV projections
    {
        dim3 grid(DD / BN, MTOT / BM, 3);
        proj_kernel<<<grid, 256>>>(x, Wq, Wk, Wv);
    }
    // 2) scores (causal block-skip inside)
    {
        dim3 grid(TT / BN, TT / BM, BB);
        scores_kernel<<<grid, 256>>>();
    }
    // 3) softmax
    {
        softmax_kernel<<<MTOT, 256>>>();
    }
    // 4) att @ V
    {
        dim3 grid(DD / BN, TT / BM, BB);
        pv_kernel<<<grid, 256>>>(out);
    }
}

// round 3
// speedup vs baseline: 3.3805x; 3.3805x over previous
#include <cuda_runtime.h>
#include <cstdint>
#include <math.h>

#define BB 4
#define TT 2048
#define DD 1024
#define MTOT (BB * TT)
#define SCALE (0.03125f)

// ---------------- scratch (no allocations allowed) ----------------
__device__ float g_q[MTOT * DD];
__device__ float g_k[MTOT * DD];
__device__ float g_v[MTOT * DD];
__device__ float g_kt[(size_t)BB * DD * TT];   // K transposed per batch: [e][t]
__device__ float g_s[(size_t)BB * TT * TT];    // scores -> att (in-place)

// ---------------- tf32 helpers ----------------
__device__ __forceinline__ uint32_t f2tf(float x) {
    uint32_t u;
    asm("cvt.rna.tf32.f32 %0, %1;" : "=r"(u) : "f"(x));
    return u;
}
__device__ __forceinline__ void mma_tf32(float* c, const uint32_t* a, const uint32_t* b) {
    asm volatile(
        "mma.sync.aligned.m16n8k8.row.col.f32.tf32.tf32.f32 "
        "{%0,%1,%2,%3}, {%4,%5,%6,%7}, {%8,%9}, {%0,%1,%2,%3};"
        : "+f"(c[0]), "+f"(c[1]), "+f"(c[2]), "+f"(c[3])
        : "r"(a[0]), "r"(a[1]), "r"(a[2]), "r"(a[3]), "r"(b[0]), "r"(b[1]));
}

// SMEM strides (words), padded for conflict-free fragment loads:
// A[m][k]: stride 20 -> banks (m*20+k)%32 all-distinct for m 0..7 x k 0..3
// B[k][n]: stride 136 -> banks (k*8+n)%32 all-distinct for k 0..3 x n 0..7
#define SA 20
#define SB 136

// ---------------------------------------------------------------------------
// 128x128 block GEMM via tf32 mma.sync.
//   A: [128, K]  row-major (lda)   -- the M operand
//   B: [K, 128]  row-major (ldb)   -- the N operand (k rows, n cols)
//   C: [128,128] row-major (ldc), scaled.
// K multiple of 16.  256 threads: warp grid 4(M) x 2(N), warp tile 32x64.
// ---------------------------------------------------------------------------
__device__ __forceinline__ void gemm128_mma(
    const float* __restrict__ A, int lda,
    const float* __restrict__ B, int ldb,
    float* __restrict__ C, int ldc,
    int K, float scale)
{
    __shared__ uint32_t As[2][128 * SA];
    __shared__ uint32_t Bs[2][16 * SB];

    const int tid = threadIdx.x;
    const int wid = tid >> 5, lane = tid & 31;
    const int g = lane >> 2, t = lane & 3;
    const int wm = wid & 3;          // warp row: 32 rows each
    const int wn = wid >> 2;         // warp col: 64 cols each

    // global->smem load mapping
    const int rowA = tid >> 2;            // 0..63 (and +64)
    const int kqA = (tid & 3) * 4;        // k word offset 0/4/8/12
    const int rowB = tid >> 5;            // 0..7 (and +8)
    const int nqB = (tid & 31) * 4;       // n word offset

    float acc[2][8][4];
#pragma unroll
    for (int mi = 0; mi < 2; mi++)
#pragma unroll
        for (int ni = 0; ni < 8; ni++)
#pragma unroll
            for (int j = 0; j < 4; j++) acc[mi][ni][j] = 0.f;

    const int nc = K >> 4;

    // prologue: stage 0
    {
        float4 a0 = *reinterpret_cast<const float4*>(A + (size_t)rowA * lda + kqA);
        float4 a1 = *reinterpret_cast<const float4*>(A + (size_t)(rowA + 64) * lda + kqA);
        float4 b0 = *reinterpret_cast<const float4*>(B + (size_t)rowB * ldb + nqB);
        float4 b1 = *reinterpret_cast<const float4*>(B + (size_t)(rowB + 8) * ldb + nqB);
        uint32_t* pa0 = &As[0][rowA * SA + kqA];
        pa0[0] = f2tf(a0.x); pa0[1] = f2tf(a0.y); pa0[2] = f2tf(a0.z); pa0[3] = f2tf(a0.w);
        uint32_t* pa1 = &As[0][(rowA + 64) * SA + kqA];
        pa1[0] = f2tf(a1.x); pa1[1] = f2tf(a1.y); pa1[2] = f2tf(a1.z); pa1[3] = f2tf(a1.w);
        uint32_t* pb0 = &Bs[0][rowB * SB + nqB];
        pb0[0] = f2tf(b0.x); pb0[1] = f2tf(b0.y); pb0[2] = f2tf(b0.z); pb0[3] = f2tf(b0.w);
        uint32_t* pb1 = &Bs[0][(rowB + 8) * SB + nqB];
        pb1[0] = f2tf(b1.x); pb1[1] = f2tf(b1.y); pb1[2] = f2tf(b1.z); pb1[3] = f2tf(b1.w);
    }
    __syncthreads();

    for (int c = 0; c < nc; c++) {
        const int buf = c & 1;
        float4 a0, a1, b0, b1;
        const bool pre = (c + 1 < nc);
        if (pre) {
            const int k0 = (c + 1) << 4;
            a0 = *reinterpret_cast<const float4*>(A + (size_t)rowA * lda + k0 + kqA);
            a1 = *reinterpret_cast<const float4*>(A + (size_t)(rowA + 64) * lda + k0 + kqA);
            b0 = *reinterpret_cast<const float4*>(B + (size_t)(k0 + rowB) * ldb + nqB);
            b1 = *reinterpret_cast<const float4*>(B + (size_t)(k0 + rowB + 8) * ldb + nqB);
        }

        // compute on buf
#pragma unroll
        for (int ks = 0; ks < 16; ks += 8) {
            uint32_t af[2][4];
#pragma unroll
            for (int mi = 0; mi < 2; mi++) {
                const int r = wm * 32 + mi * 16 + g;
                af[mi][0] = As[buf][r * SA + ks + t];
                af[mi][1] = As[buf][(r + 8) * SA + ks + t];
                af[mi][2] = As[buf][r * SA + ks + t + 4];
                af[mi][3] = As[buf][(r + 8) * SA + ks + t + 4];
            }
            uint32_t bf[8][2];
#pragma unroll
            for (int ni = 0; ni < 8; ni++) {
                const int cc = wn * 64 + ni * 8 + g;
                bf[ni][0] = Bs[buf][(ks + t) * SB + cc];
                bf[ni][1] = Bs[buf][(ks + t + 4) * SB + cc];
            }
#pragma unroll
            for (int mi = 0; mi < 2; mi++)
#pragma unroll
                for (int ni = 0; ni < 8; ni++)
                    mma_tf32(acc[mi][ni], af[mi], bf[ni]);
        }

        if (pre) {
            const int nb = buf ^ 1;
            uint32_t* pa0 = &As[nb][rowA * SA + kqA];
            pa0[0] = f2tf(a0.x); pa0[1] = f2tf(a0.y); pa0[2] = f2tf(a0.z); pa0[3] = f2tf(a0.w);
            uint32_t* pa1 = &As[nb][(rowA + 64) * SA + kqA];
            pa1[0] = f2tf(a1.x); pa1[1] = f2tf(a1.y); pa1[2] = f2tf(a1.z); pa1[3] = f2tf(a1.w);
            uint32_t* pb0 = &Bs[nb][rowB * SB + nqB];
            pb0[0] = f2tf(b0.x); pb0[1] = f2tf(b0.y); pb0[2] = f2tf(b0.z); pb0[3] = f2tf(b0.w);
            uint32_t* pb1 = &Bs[nb][(rowB + 8) * SB + nqB];
            pb1[0] = f2tf(b1.x); pb1[1] = f2tf(b1.y); pb1[2] = f2tf(b1.z); pb1[3] = f2tf(b1.w);
            __syncthreads();
        }
    }

    // epilogue: direct float2 stores (8B aligned: col = ... + 2t)
#pragma unroll
    for (int mi = 0; mi < 2; mi++) {
        const int r0 = wm * 32 + mi * 16 + g;
#pragma unroll
        for (int ni = 0; ni < 8; ni++) {
            const int col = wn * 64 + ni * 8 + 2 * t;
            float2 v0, v1;
            v0.x = acc[mi][ni][0] * scale; v0.y = acc[mi][ni][1] * scale;
            v1.x = acc[mi][ni][2] * scale; v1.y = acc[mi][ni][3] * scale;
            *reinterpret_cast<float2*>(C + (size_t)r0 * ldc + col) = v0;
            *reinterpret_cast<float2*>(C + (size_t)(r0 + 8) * ldc + col) = v1;
        }
    }
}

// ---------------------------------------------------------------------------
// GEMM wrappers
// ---------------------------------------------------------------------------
__global__ void __launch_bounds__(256, 2)
proj_mma(const float* __restrict__ x,
         const float* __restrict__ Wq, const float* __restrict__ Wk,
         const float* __restrict__ Wv)
{
    const int z = blockIdx.z;
    const float* W = (z == 0) ? Wq : (z == 1) ? Wk : Wv;   // [k][n] row-major
    float* C = ((z == 0) ? g_q : (z == 1) ? g_k : g_v)
             + (size_t)blockIdx.y * 128 * DD + blockIdx.x * 128;
    const float* A = x + (size_t)blockIdx.y * 128 * DD;
    gemm128_mma(A, DD, W + blockIdx.x * 128, DD, C, DD, DD, 1.0f);
}

__global__ void __launch_bounds__(256, 2)
scores_mma()
{
    if (blockIdx.x > blockIdx.y) return;   // fully masked tile
    const int b = blockIdx.z;
    const size_t qb = (size_t)blockIdx.y * 128, kb = (size_t)blockIdx.x * 128;
    const float* A = g_q + (size_t)b * TT * DD + qb * DD;       // [q][e]
    const float* B = g_kt + (size_t)b * DD * TT + kb;           // [e][t]
    float* C = g_s + (size_t)b * TT * TT + qb * TT + kb;
    gemm128_mma(A, DD, B, TT, C, TT, DD, SCALE);
}

__global__ void __launch_bounds__(256, 2)
pv_mma(float* __restrict__ out)
{
    const int b = blockIdx.z;
    const size_t qb = (size_t)blockIdx.y * 128, eb = (size_t)blockIdx.x * 128;
    const int kmax = (blockIdx.y + 1) * 128;  // att[q,k]=0 beyond q
    const float* A = g_s + (size_t)b * TT * TT + qb * TT;       // [q][t]
    const float* B = g_v + (size_t)b * TT * DD + eb;            // [t][e]
    float* C = out + (size_t)b * TT * DD + qb * DD + eb;
    gemm128_mma(A, TT, B, DD, C, DD, kmax, 1.0f);
}

// ---------------------------------------------------------------------------
// K transpose per batch: g_k [t][e] -> g_kt [e][t]
// ---------------------------------------------------------------------------
__global__ void __launch_bounds__(256)
transpose_k_kernel()
{
    __shared__ float tbuf[32][33];
    const int b = blockIdx.z;
    const float* Km = g_k + (size_t)b * TT * DD;
    float* KT = g_kt + (size_t)b * DD * TT;
    const int tb = blockIdx.x * 32, eb = blockIdx.y * 32;
    const int tx = threadIdx.x & 31, ty = threadIdx.x >> 5;
#pragma unroll
    for (int j = 0; j < 4; j++)
        tbuf[ty + 8 * j][tx] = Km[(size_t)(tb + ty + 8 * j) * DD + eb + tx];
    __syncthreads();
#pragma unroll
    for (int j = 0; j < 4; j++)
        KT[(size_t)(eb + ty + 8 * j) * TT + tb + tx] = tbuf[tx][ty + 8 * j];
}

// ---------------------------------------------------------------------------
// Causal softmax (in-place on g_s); zero-fills k > q.
// ---------------------------------------------------------------------------
__global__ void __launch_bounds__(256)
softmax_kernel()
{
    const int row = blockIdx.x;  // b*TT + q
    const int q = row % TT;
    float* s = g_s + (size_t)row * TT;
    const int n = q + 1;
    const int tid = threadIdx.x;
    __shared__ float red[256];

    float vals[8];
    float m = -INFINITY;
#pragma unroll
    for (int i = 0; i < 8; i++) {
        const int idx = tid + i * 256;
        vals[i] = (idx < n) ? s[idx] : -INFINITY;
        m = fmaxf(m, vals[i]);
    }
    red[tid] = m;
    __syncthreads();
    for (int off = 128; off > 0; off >>= 1) {
        if (tid < off) red[tid] = fmaxf(red[tid], red[tid + off]);
        __syncthreads();
    }
    m = red[0];
    __syncthreads();

    float sum = 0.f;
#pragma unroll
    for (int i = 0; i < 8; i++) {
        vals[i] = (tid + i * 256 < n) ? __expf(vals[i] - m) : 0.f;
        sum += vals[i];
    }
    red[tid] = sum;
    __syncthreads();
    for (int off = 128; off > 0; off >>= 1) {
        if (tid < off) red[tid] += red[tid + off];
        __syncthreads();
    }
    const float inv = 1.f / red[0];
#pragma unroll
    for (int i = 0; i < 8; i++)
        s[tid + i * 256] = vals[i] * inv;
}

// ---------------------------------------------------------------------------
extern "C" void kernel_launch(void* const* d_in, const int* in_sizes, int n_in,
                              void* d_out, int out_size)
{
    const float* x  = (const float*)d_in[0];
    const float* Wq = (const float*)d_in[1];
    const float* Wk = (const float*)d_in[2];
    const float* Wv = (const float*)d_in[3];
    float* out = (float*)d_out;

    {   // QKV projections (tensor pipe, tf32)
        dim3 grid(DD / 128, MTOT / 128, 3);
        proj_mma<<<grid, 256>>>(x, Wq, Wk, Wv);
    }
    {   // K^T
        dim3 grid(TT / 32, DD / 32, BB);
        transpose_k_kernel<<<grid, 256>>>();
    }
    {   // scores = scale * Q K^T (causal block skip)
        dim3 grid(TT / 128, TT / 128, BB);
        scores_mma<<<grid, 256>>>();
    }
    softmax_kernel<<<MTOT, 256>>>();
    {   // out = att V
        dim3 grid(DD / 128, TT / 128, BB);
        pv_mma<<<grid, 256>>>(out);
    }
}

// round 5
// speedup vs baseline: 3.7752x; 1.1168x over previous
#include <cuda_runtime.h>
#include <cstdint>
#include <math.h>

#define BB 4
#define TT 2048
#define DD 1024
#define MTOT (BB * TT)
#define SCALE (0.03125f)

// ---------------- scratch (no allocations allowed) ----------------
__device__ float g_xr[(size_t)MTOT * DD];      // x rounded to tf32
__device__ float g_wr[(size_t)3 * DD * DD];    // Wq/Wk/Wv rounded to tf32
__device__ float g_q[(size_t)MTOT * DD];       // tf32-rounded
__device__ float g_k[(size_t)MTOT * DD];       // tf32-rounded
__device__ float g_v[(size_t)MTOT * DD];       // tf32-rounded
__device__ float g_kt[(size_t)BB * DD * TT];   // K^T per batch [e][t] (rounded)
__device__ float g_s[(size_t)BB * TT * TT];    // scores -> att (att tf32-rounded)

// ---------------- helpers ----------------
__device__ __forceinline__ uint32_t f2tf(float x) {
    uint32_t u;
    asm("cvt.rna.tf32.f32 %0, %1;" : "=r"(u) : "f"(x));
    return u;
}
__device__ __forceinline__ float roundtf(float x) {
    return __uint_as_float(f2tf(x));
}
__device__ __forceinline__ void mma_tf32(float* c, const uint32_t* a, const uint32_t* b) {
    asm volatile(
        "mma.sync.aligned.m16n8k8.row.col.f32.tf32.tf32.f32 "
        "{%0,%1,%2,%3}, {%4,%5,%6,%7}, {%8,%9}, {%0,%1,%2,%3};"
        : "+f"(c[0]), "+f"(c[1]), "+f"(c[2]), "+f"(c[3])
        : "r"(a[0]), "r"(a[1]), "r"(a[2]), "r"(a[3]), "r"(b[0]), "r"(b[1]));
}
__device__ __forceinline__ uint32_t smem_u32(const void* p) {
    uint32_t a;
    asm("{ .reg .u64 t; cvta.to.shared.u64 t, %1; cvt.u32.u64 %0, t; }" : "=r"(a) : "l"(p));
    return a;
}
__device__ __forceinline__ void cpa16(uint32_t* dst, const float* src) {
    asm volatile("cp.async.cg.shared.global [%0], [%1], 16;"
                 :: "r"(smem_u32(dst)), "l"(src));
}
#define CP_COMMIT() asm volatile("cp.async.commit_group;" ::: "memory")
#define CP_WAIT1()  asm volatile("cp.async.wait_group 1;" ::: "memory")

// SMEM strides (words), conflict-free for fragment loads (validated in R3):
#define KC 16
#define STAGES 3
#define SA 20          // A tile: 128 rows x 16 words, row stride 20
#define SB 136         // B tile: 16 rows x 128 words, row stride 136
#define A_WORDS (128 * SA)                 // 2560
#define B_WORDS (KC * SB)                  // 2176
#define STAGE_WORDS (A_WORDS + B_WORDS)    // 4736
#define SMEM_BYTES (STAGES * STAGE_WORDS * 4)  // 56832

// ---------------------------------------------------------------------------
// 128x128 block GEMM via tf32 mma.sync + cp.async 3-stage pipeline.
//   A: [128, K] row-major (lda).  B: [K, 128] row-major (ldb).
//   All A/B data must be PRE-ROUNDED to tf32 (raw-bit feed).
//   C: [128,128] row-major (ldc), scaled; optionally tf32-rounded on store.
// K multiple of 32 (nc >= 2). 256 threads, 4(M)x2(N) warps, 32x64 per warp.
// ---------------------------------------------------------------------------
__device__ __forceinline__ void gemm128_cp(
    const float* __restrict__ A, int lda,
    const float* __restrict__ B, int ldb,
    float* __restrict__ C, int ldc,
    int K, float scale, bool round_out)
{
    extern __shared__ uint32_t dsm[];

    const int tid = threadIdx.x;
    const int wid = tid >> 5, lane = tid & 31;
    const int g = lane >> 2, t = lane & 3;
    const int wm = wid & 3;
    const int wn = wid >> 2;

    // cp.async mappings
    const int rowA = tid >> 2;          // 0..63 (and +64)
    const int kqA = (tid & 3) * 4;      // word offset 0/4/8/12
    const int rowB = tid >> 5;          // 0..7 (and +8)
    const int nqB = (tid & 31) * 4;

    float acc[2][8][4];
#pragma unroll
    for (int mi = 0; mi < 2; mi++)
#pragma unroll
        for (int ni = 0; ni < 8; ni++)
#pragma unroll
            for (int j = 0; j < 4; j++) acc[mi][ni][j] = 0.f;

    const int nc = K >> 4;

    auto issue = [&](int c) {
        const int k0 = c * KC;
        uint32_t* st = dsm + (c % STAGES) * STAGE_WORDS;
        cpa16(st + rowA * SA + kqA, A + (size_t)rowA * lda + k0 + kqA);
        cpa16(st + (rowA + 64) * SA + kqA, A + (size_t)(rowA + 64) * lda + k0 + kqA);
        uint32_t* bt = st + A_WORDS;
        cpa16(bt + rowB * SB + nqB, B + (size_t)(k0 + rowB) * ldb + nqB);
        cpa16(bt + (rowB + 8) * SB + nqB, B + (size_t)(k0 + rowB + 8) * ldb + nqB);
    };

    issue(0); CP_COMMIT();
    issue(1); CP_COMMIT();

    for (int c = 0; c < nc; c++) {
        CP_WAIT1();
        __syncthreads();
        const uint32_t* As = dsm + (c % STAGES) * STAGE_WORDS;
        const uint32_t* Bs = As + A_WORDS;

#pragma unroll
        for (int ks = 0; ks < KC; ks += 8) {
            uint32_t af[2][4];
#pragma unroll
            for (int mi = 0; mi < 2; mi++) {
                const int r = wm * 32 + mi * 16 + g;
                af[mi][0] = As[r * SA + ks + t];
                af[mi][1] = As[(r + 8) * SA + ks + t];
                af[mi][2] = As[r * SA + ks + t + 4];
                af[mi][3] = As[(r + 8) * SA + ks + t + 4];
            }
            uint32_t bf[8][2];
#pragma unroll
            for (int ni = 0; ni < 8; ni++) {
                const int cc = wn * 64 + ni * 8 + g;
                bf[ni][0] = Bs[(ks + t) * SB + cc];
                bf[ni][1] = Bs[(ks + t + 4) * SB + cc];
            }
#pragma unroll
            for (int mi = 0; mi < 2; mi++)
#pragma unroll
                for (int ni = 0; ni < 8; ni++)
                    mma_tf32(acc[mi][ni], af[mi], bf[ni]);
        }

        if (c + 2 < nc) issue(c + 2);
        CP_COMMIT();
    }

    // epilogue: float2 stores
#pragma unroll
    for (int mi = 0; mi < 2; mi++) {
        const int r0 = wm * 32 + mi * 16 + g;
#pragma unroll
        for (int ni = 0; ni < 8; ni++) {
            const int col = wn * 64 + ni * 8 + 2 * t;
            float2 v0, v1;
            if (round_out) {
                v0.x = roundtf(acc[mi][ni][0] * scale); v0.y = roundtf(acc[mi][ni][1] * scale);
                v1.x = roundtf(acc[mi][ni][2] * scale); v1.y = roundtf(acc[mi][ni][3] * scale);
            } else {
                v0.x = acc[mi][ni][0] * scale; v0.y = acc[mi][ni][1] * scale;
                v1.x = acc[mi][ni][2] * scale; v1.y = acc[mi][ni][3] * scale;
            }
            *reinterpret_cast<float2*>(C + (size_t)r0 * ldc + col) = v0;
            *reinterpret_cast<float2*>(C + (size_t)(r0 + 8) * ldc + col) = v1;
        }
    }
}

// ---------------------------------------------------------------------------
// GEMM wrappers (all scratch symbols referenced from DEVICE code only)
// ---------------------------------------------------------------------------
__global__ void __launch_bounds__(256, 2)
proj_mma()
{
    const int z = blockIdx.z;
    const float* W = g_wr + (size_t)z * DD * DD;
    float* C = ((z == 0) ? g_q : (z == 1) ? g_k : g_v)
             + (size_t)blockIdx.y * 128 * DD + blockIdx.x * 128;
    const float* A = g_xr + (size_t)blockIdx.y * 128 * DD;
    gemm128_cp(A, DD, W + blockIdx.x * 128, DD, C, DD, DD, 1.0f, true);
}

__global__ void __launch_bounds__(256, 2)
scores_mma()
{
    if (blockIdx.x > blockIdx.y) return;   // fully masked tile
    const int b = blockIdx.z;
    const size_t qb = (size_t)blockIdx.y * 128, kb = (size_t)blockIdx.x * 128;
    const float* A = g_q + (size_t)b * TT * DD + qb * DD;     // [q][e]
    const float* B = g_kt + (size_t)b * DD * TT + kb;         // [e][t]
    float* C = g_s + (size_t)b * TT * TT + qb * TT + kb;
    gemm128_cp(A, DD, B, TT, C, TT, DD, SCALE, false);
}

__global__ void __launch_bounds__(256, 2)
pv_mma(float* __restrict__ out)
{
    const int b = blockIdx.z;
    const size_t qb = (size_t)blockIdx.y * 128, eb = (size_t)blockIdx.x * 128;
    const int kmax = (blockIdx.y + 1) * 128;  // att[q,k]=0 beyond q
    const float* A = g_s + (size_t)b * TT * TT + qb * TT;     // [q][t]
    const float* B = g_v + (size_t)b * TT * DD + eb;          // [t][e]
    float* C = out + (size_t)b * TT * DD + qb * DD + eb;
    gemm128_cp(A, TT, B, DD, C, DD, kmax, 1.0f, false);
}

// ---------------------------------------------------------------------------
// tf32 pre-rounding passes (destinations are device symbols, named in device code)
// ---------------------------------------------------------------------------
__global__ void __launch_bounds__(256)
round_x_kernel(const float4* __restrict__ src)
{
    const int i = blockIdx.x * 256 + threadIdx.x;   // n4 = MTOT*DD/4 = 2M, exact grid
    float4 v = src[i];
    v.x = roundtf(v.x); v.y = roundtf(v.y);
    v.z = roundtf(v.z); v.w = roundtf(v.w);
    reinterpret_cast<float4*>(g_xr)[i] = v;
}

__global__ void __launch_bounds__(256)
round_w_kernel(const float4* __restrict__ Wq, const float4* __restrict__ Wk,
               const float4* __restrict__ Wv)
{
    const int n4 = DD * DD / 4;
    const int i = blockIdx.x * 256 + threadIdx.x;   // grid covers n4 exactly
    const int z = blockIdx.y;
    const float4* src = (z == 0) ? Wq : (z == 1) ? Wk : Wv;
    float4 v = src[i];
    v.x = roundtf(v.x); v.y = roundtf(v.y);
    v.z = roundtf(v.z); v.w = roundtf(v.w);
    reinterpret_cast<float4*>(g_wr)[(size_t)z * n4 + i] = v;
}

// ---------------------------------------------------------------------------
// K transpose per batch: g_k [t][e] -> g_kt [e][t]
// ---------------------------------------------------------------------------
__global__ void __launch_bounds__(256)
transpose_k_kernel()
{
    __shared__ float tbuf[32][33];
    const int b = blockIdx.z;
    const float* Km = g_k + (size_t)b * TT * DD;
    float* KT = g_kt + (size_t)b * DD * TT;
    const int tb = blockIdx.x * 32, eb = blockIdx.y * 32;
    const int tx = threadIdx.x & 31, ty = threadIdx.x >> 5;
#pragma unroll
    for (int j = 0; j < 4; j++)
        tbuf[ty + 8 * j][tx] = Km[(size_t)(tb + ty + 8 * j) * DD + eb + tx];
    __syncthreads();
#pragma unroll
    for (int j = 0; j < 4; j++)
        KT[(size_t)(eb + ty + 8 * j) * TT + tb + tx] = tbuf[tx][ty + 8 * j];
}

// ---------------------------------------------------------------------------
// Causal softmax (in-place on g_s); zero-fills k > q; rounds att to tf32.
// ---------------------------------------------------------------------------
__global__ void __launch_bounds__(256)
softmax_kernel()
{
    const int row = blockIdx.x;  // b*TT + q
    const int q = row % TT;
    float* s = g_s + (size_t)row * TT;
    const int n = q + 1;
    const int tid = threadIdx.x;
    __shared__ float red[256];

    float vals[8];
    float m = -INFINITY;
#pragma unroll
    for (int i = 0; i < 8; i++) {
        const int idx = tid + i * 256;
        vals[i] = (idx < n) ? s[idx] : -INFINITY;
        m = fmaxf(m, vals[i]);
    }
    red[tid] = m;
    __syncthreads();
    for (int off = 128; off > 0; off >>= 1) {
        if (tid < off) red[tid] = fmaxf(red[tid], red[tid + off]);
        __syncthreads();
    }
    m = red[0];
    __syncthreads();

    float sum = 0.f;
#pragma unroll
    for (int i = 0; i < 8; i++) {
        vals[i] = (tid + i * 256 < n) ? __expf(vals[i] - m) : 0.f;
        sum += vals[i];
    }
    red[tid] = sum;
    __syncthreads();
    for (int off = 128; off > 0; off >>= 1) {
        if (tid < off) red[tid] += red[tid + off];
        __syncthreads();
    }
    const float inv = 1.f / red[0];
#pragma unroll
    for (int i = 0; i < 8; i++)
        s[tid + i * 256] = roundtf(vals[i] * inv);
}

// ---------------------------------------------------------------------------
extern "C" void kernel_launch(void* const* d_in, const int* in_sizes, int n_in,
                              void* d_out, int out_size)
{
    const float* x  = (const float*)d_in[0];
    const float* Wq = (const float*)d_in[1];
    const float* Wk = (const float*)d_in[2];
    const float* Wv = (const float*)d_in[3];
    float* out = (float*)d_out;

    // unconditional (no static guards); immediate host-side API, not captured
    cudaFuncSetAttribute(proj_mma,   cudaFuncAttributeMaxDynamicSharedMemorySize, SMEM_BYTES);
    cudaFuncSetAttribute(scores_mma, cudaFuncAttributeMaxDynamicSharedMemorySize, SMEM_BYTES);
    cudaFuncSetAttribute(pv_mma,     cudaFuncAttributeMaxDynamicSharedMemorySize, SMEM_BYTES);

    // 0) pre-round x and W to tf32 (rna) so GEMMs can cp.async raw bits
    round_x_kernel<<<MTOT * DD / 4 / 256, 256>>>((const float4*)x);
    {
        dim3 grid(DD * DD / 4 / 256, 3);
        round_w_kernel<<<grid, 256>>>((const float4*)Wq, (const float4*)Wk,
                                      (const float4*)Wv);
    }
    {   // 1) QKV projections (epilogue rounds Q/K/V to tf32)
        dim3 grid(DD / 128, MTOT / 128, 3);
        proj_mma<<<grid, 256, SMEM_BYTES>>>();
    }
    {   // 2) K^T
        dim3 grid(TT / 32, DD / 32, BB);
        transpose_k_kernel<<<grid, 256>>>();
    }
    {   // 3) scores = scale * Q K^T (causal block skip)
        dim3 grid(TT / 128, TT / 128, BB);
        scores_mma<<<grid, 256, SMEM_BYTES>>>();
    }
    // 4) softmax (rounds att to tf32)
    softmax_kernel<<<MTOT, 256>>>();
    {   // 5) out = att V
        dim3 grid(DD / 128, TT / 128, BB);
        pv_mma<<<grid, 256, SMEM_BYTES>>>(out);
    }
}